// round 2
// baseline (speedup 1.0000x reference)
#include <cuda_runtime.h>
#include <math.h>

#define B_ 16
#define N_ 2048
#define C_ 512
#define D_ 64

// Scratch for Q[b][n][d], K[b][n][d], V[b][n][c]  (static device globals: allowed)
__device__ float g_Q[B_ * N_ * D_];
__device__ float g_K[B_ * N_ * D_];
__device__ float g_V[B_ * N_ * C_];

// ---------------------------------------------------------------------------
// Projection GEMM: out[m, o] = sum_c X[m, c] * W[o, c] + bias[o]
// M = B*N = 32768, K = 512, Dout = 64 (Q,K) or 512 (V)
// Tile: 64 (M) x 16*KC (O), 256 threads, each thread 4 rows x KC cols.
// Smem stored k-major: Xs[kk][row], Ws[kk][o]  -> conflict-free inner loads.
// which: 0 -> g_Q, 1 -> g_K, 2 -> g_V
// ---------------------------------------------------------------------------
template <int KC>
__global__ __launch_bounds__(256) void proj_kernel(
    const float* __restrict__ X, const float* __restrict__ W,
    const float* __restrict__ bias, int which, int Dout)
{
    constexpr int TO = 16 * KC;
    __shared__ float Xs[16 * 64];
    __shared__ float Ws[16 * TO];

    float* out = (which == 0) ? g_Q : (which == 1) ? g_K : g_V;

    const int tid = threadIdx.x;
    const int tx = tid & 15, ty = tid >> 4;
    const int m0 = blockIdx.y * 64;
    const int o0 = blockIdx.x * TO;

    float acc[4][KC];
#pragma unroll
    for (int r = 0; r < 4; r++)
#pragma unroll
        for (int k = 0; k < KC; k++) acc[r][k] = 0.f;

    for (int kt = 0; kt < C_; kt += 16) {
        // X tile: 64 rows x 16 k-vals, transposed into Xs[kk][row]
        {
            int row = tid >> 2, c4 = (tid & 3) * 4;
            float4 v = *(const float4*)(X + (size_t)(m0 + row) * C_ + kt + c4);
            Xs[(c4 + 0) * 64 + row] = v.x;
            Xs[(c4 + 1) * 64 + row] = v.y;
            Xs[(c4 + 2) * 64 + row] = v.z;
            Xs[(c4 + 3) * 64 + row] = v.w;
        }
        // W tile: TO rows x 16 k-vals, transposed into Ws[kk][o]
#pragma unroll
        for (int l = 0; l < KC / 4; l++) {
            int f = tid + l * 256;
            int o = f >> 2, c4 = (f & 3) * 4;
            float4 v = *(const float4*)(W + (size_t)(o0 + o) * C_ + kt + c4);
            Ws[(c4 + 0) * TO + o] = v.x;
            Ws[(c4 + 1) * TO + o] = v.y;
            Ws[(c4 + 2) * TO + o] = v.z;
            Ws[(c4 + 3) * TO + o] = v.w;
        }
        __syncthreads();
#pragma unroll
        for (int kk = 0; kk < 16; kk++) {
            float a[4];
#pragma unroll
            for (int r = 0; r < 4; r++) a[r] = Xs[kk * 64 + 4 * ty + r];
#pragma unroll
            for (int k = 0; k < KC; k++) {
                float w = Ws[kk * TO + tx + 16 * k];
#pragma unroll
                for (int r = 0; r < 4; r++) acc[r][k] += a[r] * w;
            }
        }
        __syncthreads();
    }

#pragma unroll
    for (int k = 0; k < KC; k++) {
        int o = o0 + tx + 16 * k;
        float bvv = bias[o];
#pragma unroll
        for (int r = 0; r < 4; r++) {
            int m = m0 + 4 * ty + r;
            out[(size_t)m * Dout + o] = acc[r][k] + bvv;
        }
    }
}

// ---------------------------------------------------------------------------
// Flash attention (no 1/sqrt(d) scale, non-causal) + residual epilogue.
// Block: (cs: 1 of 4 slices of 128 V-channels, qt: 1 of 32 q-tiles of 64 rows,
//         b: batch). 256 threads; O accumulator 64x128 in registers (4x8/thr).
// Online softmax over 32 key tiles of 64.
// ---------------------------------------------------------------------------
__global__ __launch_bounds__(256, 2) void attn_kernel(
    const float* __restrict__ x, const float* __restrict__ gamma_p,
    float* __restrict__ out)
{
    extern __shared__ float sm[];
    float* Qs = sm;                  // 64*64
    float* Ks = Qs + 64 * 64;        // 64*65 (pad 1: conflict-free K reads)
    float* Ss = Ks + 64 * 65;        // 64*65
    float* Vs = Ss + 64 * 65;        // 64*128
    float* row_m = Vs + 64 * 128;    // 64
    float* row_l = row_m + 64;       // 64
    float* row_scale = row_l + 64;   // 64

    const int tid = threadIdx.x;
    const int tx = tid & 15, ty = tid >> 4;
    const int cs = blockIdx.x, qt = blockIdx.y, b = blockIdx.z;

    const float* Qg = g_Q + ((size_t)b * N_ + qt * 64) * D_;
    const float* Kg = g_K + (size_t)b * N_ * D_;
    const float* Vg = g_V + (size_t)b * N_ * C_ + cs * 128;

    // Load Q tile (64x64), stride 64 in smem
#pragma unroll
    for (int l = 0; l < 4; l++) {
        int f = tid + l * 256;
        int row = f >> 4, c4 = (f & 15) * 4;
        *(float4*)(Qs + row * 64 + c4) = *(const float4*)(Qg + row * D_ + c4);
    }
    if (tid < 64) { row_m[tid] = -INFINITY; row_l[tid] = 0.f; }

    float acc[4][8];
#pragma unroll
    for (int r = 0; r < 4; r++)
#pragma unroll
        for (int k = 0; k < 8; k++) acc[r][k] = 0.f;

    for (int mt = 0; mt < N_ / 64; mt++) {
        // K tile 64x64 -> Ks (stride 65)
#pragma unroll
        for (int l = 0; l < 4; l++) {
            int f = tid + l * 256;
            int row = f >> 4, c4 = (f & 15) * 4;
            float4 v = *(const float4*)(Kg + (size_t)(mt * 64 + row) * D_ + c4);
            float* d = Ks + row * 65 + c4;
            d[0] = v.x; d[1] = v.y; d[2] = v.z; d[3] = v.w;
        }
        // V tile 64x128 -> Vs (stride 128)
#pragma unroll
        for (int l = 0; l < 8; l++) {
            int f = tid + l * 256;
            int row = f >> 5, c4 = (f & 31) * 4;
            *(float4*)(Vs + row * 128 + c4) =
                *(const float4*)(Vg + (size_t)(mt * 64 + row) * C_ + c4);
        }
        __syncthreads();

        // S = Q * K^T : rows i = 4*ty+r, cols j = tx + 16*k
        float s[4][4];
#pragma unroll
        for (int r = 0; r < 4; r++)
#pragma unroll
            for (int k = 0; k < 4; k++) s[r][k] = 0.f;
#pragma unroll 8
        for (int d = 0; d < 64; d++) {
            float q[4];
#pragma unroll
            for (int r = 0; r < 4; r++) q[r] = Qs[(4 * ty + r) * 64 + d];
#pragma unroll
            for (int k = 0; k < 4; k++) {
                float kv = Ks[(tx + 16 * k) * 65 + d];
#pragma unroll
                for (int r = 0; r < 4; r++) s[r][k] += q[r] * kv;
            }
        }
#pragma unroll
        for (int r = 0; r < 4; r++)
#pragma unroll
            for (int k = 0; k < 4; k++)
                Ss[(4 * ty + r) * 65 + tx + 16 * k] = s[r][k];
        __syncthreads();

        // Online softmax: one thread per row (stride-65 => conflict-free)
        if (tid < 64) {
            float* Srow = Ss + tid * 65;
            float mo = row_m[tid];
            float mx = mo;
#pragma unroll 16
            for (int j = 0; j < 64; j++) mx = fmaxf(mx, Srow[j]);
            float sc = __expf(mo - mx);
            float l = row_l[tid] * sc;
#pragma unroll 16
            for (int j = 0; j < 64; j++) {
                float p = __expf(Srow[j] - mx);
                Srow[j] = p;
                l += p;
            }
            row_m[tid] = mx; row_l[tid] = l; row_scale[tid] = sc;
        }
        __syncthreads();

        // Rescale accumulator, then O += P * V
        float scr[4];
#pragma unroll
        for (int r = 0; r < 4; r++) scr[r] = row_scale[4 * ty + r];
#pragma unroll
        for (int r = 0; r < 4; r++)
#pragma unroll
            for (int k = 0; k < 8; k++) acc[r][k] *= scr[r];
#pragma unroll 4
        for (int d = 0; d < 64; d++) {
            float p[4];
#pragma unroll
            for (int r = 0; r < 4; r++) p[r] = Ss[(4 * ty + r) * 65 + d];
#pragma unroll
            for (int k = 0; k < 8; k++) {
                float v = Vs[d * 128 + tx + 16 * k];
#pragma unroll
                for (int r = 0; r < 4; r++) acc[r][k] += p[r] * v;
            }
        }
        __syncthreads();
    }

    // Epilogue: out = gamma * (O / l) + x
    const float ga = gamma_p[0];
#pragma unroll
    for (int r = 0; r < 4; r++) {
        int n = qt * 64 + 4 * ty + r;
        float inv_l = 1.f / row_l[4 * ty + r];
        size_t base = ((size_t)b * N_ + n) * C_;
#pragma unroll
        for (int k = 0; k < 8; k++) {
            int c = cs * 128 + tx + 16 * k;
            out[base + c] = ga * acc[r][k] * inv_l + x[base + c];
        }
    }
}

// ---------------------------------------------------------------------------
extern "C" void kernel_launch(void* const* d_in, const int* in_sizes, int n_in,
                              void* d_out, int out_size)
{
    const float* x     = (const float*)d_in[0];
    const float* Wq    = (const float*)d_in[1];
    const float* bq    = (const float*)d_in[2];
    const float* Wk    = (const float*)d_in[3];
    const float* bk    = (const float*)d_in[4];
    const float* Wv    = (const float*)d_in[5];
    const float* bv    = (const float*)d_in[6];
    const float* gamma = (const float*)d_in[7];
    float* out = (float*)d_out;

    const int MROWS = (B_ * N_) / 64;  // 512

    proj_kernel<4><<<dim3(1, MROWS), 256>>>(x, Wq, bq, 0, D_);
    proj_kernel<4><<<dim3(1, MROWS), 256>>>(x, Wk, bk, 1, D_);
    proj_kernel<8><<<dim3(C_ / 128, MROWS), 256>>>(x, Wv, bv, 2, C_);

    const int smem_bytes = (64 * 64 + 2 * 64 * 65 + 64 * 128 + 192) * 4; // 83200
    cudaFuncSetAttribute(attn_kernel,
                         cudaFuncAttributeMaxDynamicSharedMemorySize, smem_bytes);
    attn_kernel<<<dim3(C_ / 128, N_ / 64, B_), 256, smem_bytes>>>(x, gamma, out);
}

// round 5
// speedup vs baseline: 2.8879x; 2.8879x over previous
#include <cuda_runtime.h>
#include <math.h>

#define B_ 16
#define N_ 2048
#define C_ 512
#define D_ 64

__device__ float g_Q[B_ * N_ * D_];
__device__ float g_K[B_ * N_ * D_];
__device__ float g_V[B_ * N_ * C_];

// m16n8k8 tf32 mma. A row-major (m x k), B col-major (k x n), C f32.
// lane: g = lane>>2 (group), t = lane&3.
// A: a0=(g,t) a1=(g+8,t) a2=(g,t+4) a3=(g+8,t+4)
// B: b0=(k=t,n=g) b1=(k=t+4,n=g)
// C: c0=(g,2t) c1=(g,2t+1) c2=(g+8,2t) c3=(g+8,2t+1)
__device__ __forceinline__ void mma_tf32(float c[4], unsigned a0, unsigned a1,
                                         unsigned a2, unsigned a3,
                                         unsigned b0, unsigned b1)
{
    asm volatile(
        "mma.sync.aligned.m16n8k8.row.col.f32.tf32.tf32.f32 "
        "{%0,%1,%2,%3}, {%4,%5,%6,%7}, {%8,%9}, {%0,%1,%2,%3};\n"
        : "+f"(c[0]), "+f"(c[1]), "+f"(c[2]), "+f"(c[3])
        : "r"(a0), "r"(a1), "r"(a2), "r"(a3), "r"(b0), "r"(b1));
}
#define F2U(x) __float_as_uint(x)

// ---------------------------------------------------------------------------
// Fused projection GEMM (tf32 tensor cores).
// out[m, o] = sum_c X[m,c] * W[o,c] + bias[o]
// blockIdx.x in [0,10): 0 -> Q, 1 -> K, 2..9 -> V o-slice (o0 = (x-2)*64)
// Block: 64 (m) x 64 (o), 256 threads (8 warps, each 16m x 32o).
// ---------------------------------------------------------------------------
__global__ __launch_bounds__(256) void proj_kernel(
    const float* __restrict__ X,
    const float* __restrict__ Wq, const float* __restrict__ bq,
    const float* __restrict__ Wk, const float* __restrict__ bk,
    const float* __restrict__ Wv, const float* __restrict__ bv)
{
    __shared__ float Xs[64 * 68];
    __shared__ float Ws[64 * 68];

    const int tid = threadIdx.x;
    const int warp = tid >> 5, lane = tid & 31;
    const int g = lane >> 2, t = lane & 3;
    const int m0 = blockIdx.y * 64;
    const int wm = (warp >> 1) * 16;        // warp m offset in tile
    const int wn = (warp & 1) * 32;         // warp o offset in tile

    const float* Wp; const float* biasp; float* out; int Dout, o0;
    if (blockIdx.x == 0)      { Wp = Wq; biasp = bq; out = g_Q; Dout = 64;  o0 = 0; }
    else if (blockIdx.x == 1) { Wp = Wk; biasp = bk; out = g_K; Dout = 64;  o0 = 0; }
    else { o0 = (blockIdx.x - 2) * 64; Wp = Wv + (size_t)o0 * C_; biasp = bv + o0;
           out = g_V; Dout = C_; }

    float acc[4][4];
#pragma unroll
    for (int j = 0; j < 4; j++)
#pragma unroll
        for (int i = 0; i < 4; i++) acc[j][i] = 0.f;

    for (int kt = 0; kt < C_; kt += 64) {
#pragma unroll
        for (int l = 0; l < 4; l++) {
            int f = tid + l * 256;
            int row = f >> 4, c4 = (f & 15) * 4;
            *(float4*)(Xs + row * 68 + c4) =
                *(const float4*)(X + (size_t)(m0 + row) * C_ + kt + c4);
            *(float4*)(Ws + row * 68 + c4) =
                *(const float4*)(Wp + (size_t)row * C_ + kt + c4);
        }
        __syncthreads();
#pragma unroll
        for (int kk = 0; kk < 8; kk++) {
            int k0 = kk * 8;
            unsigned a0 = F2U(Xs[(wm + g) * 68 + k0 + t]);
            unsigned a1 = F2U(Xs[(wm + 8 + g) * 68 + k0 + t]);
            unsigned a2 = F2U(Xs[(wm + g) * 68 + k0 + t + 4]);
            unsigned a3 = F2U(Xs[(wm + 8 + g) * 68 + k0 + t + 4]);
#pragma unroll
            for (int j = 0; j < 4; j++) {
                int n = wn + 8 * j;
                unsigned b0 = F2U(Ws[(n + g) * 68 + k0 + t]);
                unsigned b1 = F2U(Ws[(n + g) * 68 + k0 + t + 4]);
                mma_tf32(acc[j], a0, a1, a2, a3, b0, b1);
            }
        }
        __syncthreads();
    }

#pragma unroll
    for (int j = 0; j < 4; j++) {
        int col = wn + 8 * j + 2 * t;
        float bv0 = biasp[col], bv1 = biasp[col + 1];
        size_t r0 = (size_t)(m0 + wm + g) * Dout + o0 + col;
        size_t r1 = (size_t)(m0 + wm + 8 + g) * Dout + o0 + col;
        out[r0]     = acc[j][0] + bv0;
        out[r0 + 1] = acc[j][1] + bv1;
        out[r1]     = acc[j][2] + bv0;
        out[r1 + 1] = acc[j][3] + bv1;
    }
}

// ---------------------------------------------------------------------------
// Flash attention (tf32 tensor cores) + residual epilogue.
// Grid: (cs: 4 slices of 128 channels, qt: 32 q-tiles of 64 rows, b: batch)
// 256 threads (8 warps). S-GEMM: warp tile 16x32; PV: warp tile 16x64.
// smem strides: Q/K/S = 68, V = 136 (conflict-free mma fragment loads).
// ---------------------------------------------------------------------------
__global__ __launch_bounds__(256, 2) void attn_kernel(
    const float* __restrict__ x, const float* __restrict__ gamma_p,
    float* __restrict__ out)
{
    extern __shared__ float sm[];
    float* Qs = sm;                    // 64*68
    float* Ks = Qs + 64 * 68;          // 64*68
    float* Ss = Ks + 64 * 68;          // 64*68
    float* Vs = Ss + 64 * 68;          // 64*136
    float* row_m = Vs + 64 * 136;      // 64
    float* row_l = row_m + 64;         // 64
    float* row_scale = row_l + 64;     // 64

    const int tid = threadIdx.x;
    const int warp = tid >> 5, lane = tid & 31;
    const int g = lane >> 2, t = lane & 3;
    const int cs = blockIdx.x, qt = blockIdx.y, b = blockIdx.z;
    const int wm = (warp >> 1) * 16;
    const int wns = (warp & 1) * 32;   // S-gemm n offset
    const int wnv = (warp & 1) * 64;   // PV n offset

    const float* Qg = g_Q + ((size_t)b * N_ + qt * 64) * D_;
    const float* Kg = g_K + (size_t)b * N_ * D_;
    const float* Vg = g_V + (size_t)b * N_ * C_ + cs * 128;

#pragma unroll
    for (int l = 0; l < 4; l++) {
        int f = tid + l * 256;
        int row = f >> 4, c4 = (f & 15) * 4;
        *(float4*)(Qs + row * 68 + c4) = *(const float4*)(Qg + row * D_ + c4);
    }
    if (tid < 64) { row_m[tid] = -INFINITY; row_l[tid] = 0.f; }

    float acc[8][4];
#pragma unroll
    for (int j = 0; j < 8; j++)
#pragma unroll
        for (int i = 0; i < 4; i++) acc[j][i] = 0.f;

    for (int mt = 0; mt < N_ / 64; mt++) {
        // Load K tile 64x64 (stride 68) and V tile 64x128 (stride 136)
#pragma unroll
        for (int l = 0; l < 4; l++) {
            int f = tid + l * 256;
            int row = f >> 4, c4 = (f & 15) * 4;
            *(float4*)(Ks + row * 68 + c4) =
                *(const float4*)(Kg + (size_t)(mt * 64 + row) * D_ + c4);
        }
#pragma unroll
        for (int l = 0; l < 8; l++) {
            int f = tid + l * 256;
            int row = f >> 5, c4 = (f & 31) * 4;
            *(float4*)(Vs + row * 136 + c4) =
                *(const float4*)(Vg + (size_t)(mt * 64 + row) * C_ + c4);
        }
        __syncthreads();

        // ---- S = Q * K^T (64x64x64) ----
        float sc4[4][4];
#pragma unroll
        for (int j = 0; j < 4; j++)
#pragma unroll
            for (int i = 0; i < 4; i++) sc4[j][i] = 0.f;
#pragma unroll
        for (int kk = 0; kk < 8; kk++) {
            int k0 = kk * 8;
            unsigned a0 = F2U(Qs[(wm + g) * 68 + k0 + t]);
            unsigned a1 = F2U(Qs[(wm + 8 + g) * 68 + k0 + t]);
            unsigned a2 = F2U(Qs[(wm + g) * 68 + k0 + t + 4]);
            unsigned a3 = F2U(Qs[(wm + 8 + g) * 68 + k0 + t + 4]);
#pragma unroll
            for (int j = 0; j < 4; j++) {
                int n = wns + 8 * j;
                unsigned b0 = F2U(Ks[(n + g) * 68 + k0 + t]);
                unsigned b1 = F2U(Ks[(n + g) * 68 + k0 + t + 4]);
                mma_tf32(sc4[j], a0, a1, a2, a3, b0, b1);
            }
        }
#pragma unroll
        for (int j = 0; j < 4; j++) {
            int col = wns + 8 * j + 2 * t;
            float* r0 = Ss + (wm + g) * 68 + col;
            float* r1 = Ss + (wm + 8 + g) * 68 + col;
            r0[0] = sc4[j][0]; r0[1] = sc4[j][1];
            r1[0] = sc4[j][2]; r1[1] = sc4[j][3];
        }
        __syncthreads();

        // ---- online softmax: 4 threads per row, stride-4 cols ----
        {
            int r = tid >> 2, q = tid & 3;
            float* Srow = Ss + r * 68 + q;
            float mo = row_m[r];
            float mx = mo;
#pragma unroll
            for (int i = 0; i < 16; i++) mx = fmaxf(mx, Srow[4 * i]);
            mx = fmaxf(mx, __shfl_xor_sync(0xffffffffu, mx, 1));
            mx = fmaxf(mx, __shfl_xor_sync(0xffffffffu, mx, 2));
            float sum = 0.f;
#pragma unroll
            for (int i = 0; i < 16; i++) {
                float p = __expf(Srow[4 * i] - mx);
                Srow[4 * i] = p;
                sum += p;
            }
            sum += __shfl_xor_sync(0xffffffffu, sum, 1);
            sum += __shfl_xor_sync(0xffffffffu, sum, 2);
            if (q == 0) {
                float scl = __expf(mo - mx);
                row_l[r] = row_l[r] * scl + sum;
                row_m[r] = mx;
                row_scale[r] = scl;
            }
        }
        __syncthreads();

        // ---- rescale accumulator, O += P * V (64x128x64) ----
        float s0 = row_scale[wm + g], s1 = row_scale[wm + 8 + g];
#pragma unroll
        for (int j = 0; j < 8; j++) {
            acc[j][0] *= s0; acc[j][1] *= s0;
            acc[j][2] *= s1; acc[j][3] *= s1;
        }
#pragma unroll
        for (int kk = 0; kk < 8; kk++) {
            int k0 = kk * 8;
            unsigned a0 = F2U(Ss[(wm + g) * 68 + k0 + t]);
            unsigned a1 = F2U(Ss[(wm + 8 + g) * 68 + k0 + t]);
            unsigned a2 = F2U(Ss[(wm + g) * 68 + k0 + t + 4]);
            unsigned a3 = F2U(Ss[(wm + 8 + g) * 68 + k0 + t + 4]);
#pragma unroll
            for (int j = 0; j < 8; j++) {
                int n = wnv + 8 * j;
                unsigned b0 = F2U(Vs[(k0 + t) * 136 + n + g]);
                unsigned b1 = F2U(Vs[(k0 + t + 4) * 136 + n + g]);
                mma_tf32(acc[j], a0, a1, a2, a3, b0, b1);
            }
        }
        __syncthreads();
    }

    // ---- epilogue: out = gamma * (O / l) + x ----
    const float ga = gamma_p[0];
    float inv0 = 1.f / row_l[wm + g];
    float inv1 = 1.f / row_l[wm + 8 + g];
    size_t base0 = ((size_t)b * N_ + qt * 64 + wm + g) * C_ + cs * 128;
    size_t base1 = ((size_t)b * N_ + qt * 64 + wm + 8 + g) * C_ + cs * 128;
#pragma unroll
    for (int j = 0; j < 8; j++) {
        int col = wnv + 8 * j + 2 * t;
        out[base0 + col]     = ga * acc[j][0] * inv0 + x[base0 + col];
        out[base0 + col + 1] = ga * acc[j][1] * inv0 + x[base0 + col + 1];
        out[base1 + col]     = ga * acc[j][2] * inv1 + x[base1 + col];
        out[base1 + col + 1] = ga * acc[j][3] * inv1 + x[base1 + col + 1];
    }
}

// ---------------------------------------------------------------------------
extern "C" void kernel_launch(void* const* d_in, const int* in_sizes, int n_in,
                              void* d_out, int out_size)
{
    const float* x     = (const float*)d_in[0];
    const float* Wq    = (const float*)d_in[1];
    const float* bq    = (const float*)d_in[2];
    const float* Wk    = (const float*)d_in[3];
    const float* bk    = (const float*)d_in[4];
    const float* Wv    = (const float*)d_in[5];
    const float* bv    = (const float*)d_in[6];
    const float* gamma = (const float*)d_in[7];
    float* out = (float*)d_out;

    proj_kernel<<<dim3(10, (B_ * N_) / 64), 256>>>(x, Wq, bq, Wk, bk, Wv, bv);

    const int smem_bytes = (3 * 64 * 68 + 64 * 136 + 192) * 4;  // 87808
    static int smem_set = 0;
    if (!smem_set) {
        cudaFuncSetAttribute(attn_kernel,
                             cudaFuncAttributeMaxDynamicSharedMemorySize, smem_bytes);
        smem_set = 1;
    }
    attn_kernel<<<dim3(C_ / 128, N_ / 64, B_), 256, smem_bytes>>>(x, gamma, out);
}

// round 6
// speedup vs baseline: 5.6083x; 1.9420x over previous
#include <cuda_runtime.h>
#include <cuda_fp16.h>
#include <math.h>

#define B_ 16
#define N_ 2048
#define C_ 512
#define D_ 64

__device__ __half g_Qh[B_ * N_ * D_];
__device__ __half g_Kh[B_ * N_ * D_];
__device__ __half g_Vt[B_ * C_ * N_];   // transposed: [b][c][n]

// ---- tf32 mma (projections) ----
__device__ __forceinline__ void mma_tf32(float c[4], unsigned a0, unsigned a1,
                                         unsigned a2, unsigned a3,
                                         unsigned b0, unsigned b1)
{
    asm volatile(
        "mma.sync.aligned.m16n8k8.row.col.f32.tf32.tf32.f32 "
        "{%0,%1,%2,%3}, {%4,%5,%6,%7}, {%8,%9}, {%0,%1,%2,%3};\n"
        : "+f"(c[0]), "+f"(c[1]), "+f"(c[2]), "+f"(c[3])
        : "r"(a0), "r"(a1), "r"(a2), "r"(a3), "r"(b0), "r"(b1));
}
// ---- fp16 mma, f32 accum (attention) ----
__device__ __forceinline__ void mma_f16(float c[4], unsigned a0, unsigned a1,
                                        unsigned a2, unsigned a3,
                                        unsigned b0, unsigned b1)
{
    asm volatile(
        "mma.sync.aligned.m16n8k16.row.col.f32.f16.f16.f32 "
        "{%0,%1,%2,%3}, {%4,%5,%6,%7}, {%8,%9}, {%0,%1,%2,%3};\n"
        : "+f"(c[0]), "+f"(c[1]), "+f"(c[2]), "+f"(c[3])
        : "r"(a0), "r"(a1), "r"(a2), "r"(a3), "r"(b0), "r"(b1));
}
#define F2U(x) __float_as_uint(x)
__device__ __forceinline__ unsigned pack_h2(float lo, float hi) {
    __half2 h = __floats2half2_rn(lo, hi);
    return *(unsigned*)&h;
}

// ---------------------------------------------------------------------------
// Fused projection GEMM (tf32): out[m,o] = sum_c X[m,c]*W[o,c] + bias[o]
// blockIdx.x: 0 -> Qh, 1 -> Kh, 2..9 -> Vt o-slice. Emits __half.
// ---------------------------------------------------------------------------
__global__ __launch_bounds__(256) void proj_kernel(
    const float* __restrict__ X,
    const float* __restrict__ Wq, const float* __restrict__ bq,
    const float* __restrict__ Wk, const float* __restrict__ bk,
    const float* __restrict__ Wv, const float* __restrict__ bv)
{
    __shared__ float Xs[64 * 68];
    __shared__ float Ws[64 * 68];

    const int tid = threadIdx.x;
    const int warp = tid >> 5, lane = tid & 31;
    const int g = lane >> 2, t = lane & 3;
    const int m0 = blockIdx.y * 64;
    const int wm = (warp >> 1) * 16;
    const int wn = (warp & 1) * 32;

    const float* Wp; const float* biasp; int o0;
    if (blockIdx.x == 0)      { Wp = Wq; biasp = bq; o0 = 0; }
    else if (blockIdx.x == 1) { Wp = Wk; biasp = bk; o0 = 0; }
    else { o0 = (blockIdx.x - 2) * 64; Wp = Wv + (size_t)o0 * C_; biasp = bv + o0; }

    float acc[4][4];
#pragma unroll
    for (int j = 0; j < 4; j++)
#pragma unroll
        for (int i = 0; i < 4; i++) acc[j][i] = 0.f;

    for (int kt = 0; kt < C_; kt += 64) {
#pragma unroll
        for (int l = 0; l < 4; l++) {
            int f = tid + l * 256;
            int row = f >> 4, c4 = (f & 15) * 4;
            *(float4*)(Xs + row * 68 + c4) =
                *(const float4*)(X + (size_t)(m0 + row) * C_ + kt + c4);
            *(float4*)(Ws + row * 68 + c4) =
                *(const float4*)(Wp + (size_t)row * C_ + kt + c4);
        }
        __syncthreads();
#pragma unroll
        for (int kk = 0; kk < 8; kk++) {
            int k0 = kk * 8;
            unsigned a0 = F2U(Xs[(wm + g) * 68 + k0 + t]);
            unsigned a1 = F2U(Xs[(wm + 8 + g) * 68 + k0 + t]);
            unsigned a2 = F2U(Xs[(wm + g) * 68 + k0 + t + 4]);
            unsigned a3 = F2U(Xs[(wm + 8 + g) * 68 + k0 + t + 4]);
#pragma unroll
            for (int j = 0; j < 4; j++) {
                int n = wn + 8 * j;
                unsigned b0 = F2U(Ws[(n + g) * 68 + k0 + t]);
                unsigned b1 = F2U(Ws[(n + g) * 68 + k0 + t + 4]);
                mma_tf32(acc[j], a0, a1, a2, a3, b0, b1);
            }
        }
        __syncthreads();
    }

    if (blockIdx.x < 2) {
        __half* outh = (blockIdx.x == 0) ? g_Qh : g_Kh;
#pragma unroll
        for (int j = 0; j < 4; j++) {
            int col = wn + 8 * j + 2 * t;
            float bv0 = biasp[col], bv1 = biasp[col + 1];
            __half2 h0 = __floats2half2_rn(acc[j][0] + bv0, acc[j][1] + bv1);
            __half2 h1 = __floats2half2_rn(acc[j][2] + bv0, acc[j][3] + bv1);
            *(__half2*)(outh + (size_t)(m0 + wm + g) * D_ + col) = h0;
            *(__half2*)(outh + (size_t)(m0 + wm + 8 + g) * D_ + col) = h1;
        }
    } else {
        // V: write transposed Vt[b][c][n]
        int bb = m0 >> 11;              // / N_
        int nn = m0 & (N_ - 1);
#pragma unroll
        for (int j = 0; j < 4; j++) {
            int col = wn + 8 * j + 2 * t;
            float bv0 = biasp[col], bv1 = biasp[col + 1];
            size_t c0b = ((size_t)bb * C_ + o0 + col) * N_;
            size_t c1b = c0b + N_;
            g_Vt[c0b + nn + wm + g]     = __float2half(acc[j][0] + bv0);
            g_Vt[c1b + nn + wm + g]     = __float2half(acc[j][1] + bv1);
            g_Vt[c0b + nn + wm + 8 + g] = __float2half(acc[j][2] + bv0);
            g_Vt[c1b + nn + wm + 8 + g] = __float2half(acc[j][3] + bv1);
        }
    }
}

// ---------------------------------------------------------------------------
// Flash attention, fp16 m16n8k16, softmax + P entirely in registers.
// Grid (cs=4 channel slices of 128, qt=32 q-tiles of 64, b=16). 128 threads.
// Warp w owns q-rows [16w, 16w+16) and the FULL 64-key S band.
// smem rows padded to 72 halves -> all fragment LDS are conflict-free.
// ---------------------------------------------------------------------------
__global__ __launch_bounds__(128, 3) void attn_kernel(
    const float* __restrict__ x, const float* __restrict__ gamma_p,
    float* __restrict__ out)
{
    __shared__ __half Qs[64 * 72];
    __shared__ __half Ks[64 * 72];
    __shared__ __half Vs[128 * 72];

    const int tid = threadIdx.x;
    const int warp = tid >> 5, lane = tid & 31;
    const int g = lane >> 2, t = lane & 3;
    const int cs = blockIdx.x, qt = blockIdx.y, b = blockIdx.z;
    const int wm = warp * 16;

    const __half* Qg = g_Qh + ((size_t)b * N_ + qt * 64) * D_;
    const __half* Kg = g_Kh + (size_t)b * N_ * D_;
    const __half* Vg = g_Vt + ((size_t)b * C_ + cs * 128) * N_;

    // Q tile: 64 rows x 64 halves
#pragma unroll
    for (int l = 0; l < 4; l++) {
        int f = tid + l * 128;
        int row = f >> 3, c8 = (f & 7) * 8;
        *(uint4*)(Qs + row * 72 + c8) = *(const uint4*)(Qg + row * D_ + c8);
    }

    float m0r = -INFINITY, m1r = -INFINITY, l0r = 0.f, l1r = 0.f;
    float acc[16][4];
#pragma unroll
    for (int j = 0; j < 16; j++)
#pragma unroll
        for (int i = 0; i < 4; i++) acc[j][i] = 0.f;

    for (int mt = 0; mt < N_ / 64; mt++) {
        // K tile 64x64
#pragma unroll
        for (int l = 0; l < 4; l++) {
            int f = tid + l * 128;
            int row = f >> 3, c8 = (f & 7) * 8;
            *(uint4*)(Ks + row * 72 + c8) =
                *(const uint4*)(Kg + (size_t)(mt * 64 + row) * D_ + c8);
        }
        // V tile (transposed): 128 channel-rows x 64 keys
#pragma unroll
        for (int l = 0; l < 8; l++) {
            int f = tid + l * 128;
            int row = f >> 3, c8 = (f & 7) * 8;
            *(uint4*)(Vs + row * 72 + c8) =
                *(const uint4*)(Vg + (size_t)row * N_ + mt * 64 + c8);
        }
        __syncthreads();

        // ---- S = Q * K^T : warp tile 16 x 64 ----
        float sc[8][4];
#pragma unroll
        for (int j = 0; j < 8; j++)
#pragma unroll
            for (int i = 0; i < 4; i++) sc[j][i] = 0.f;
#pragma unroll
        for (int kk = 0; kk < 4; kk++) {
            int k0 = kk * 16;
            unsigned a0 = *(const unsigned*)(Qs + (wm + g) * 72 + k0 + 2 * t);
            unsigned a1 = *(const unsigned*)(Qs + (wm + 8 + g) * 72 + k0 + 2 * t);
            unsigned a2 = *(const unsigned*)(Qs + (wm + g) * 72 + k0 + 2 * t + 8);
            unsigned a3 = *(const unsigned*)(Qs + (wm + 8 + g) * 72 + k0 + 2 * t + 8);
#pragma unroll
            for (int j = 0; j < 8; j++) {
                unsigned b0 = *(const unsigned*)(Ks + (8 * j + g) * 72 + k0 + 2 * t);
                unsigned b1 = *(const unsigned*)(Ks + (8 * j + g) * 72 + k0 + 2 * t + 8);
                mma_f16(sc[j], a0, a1, a2, a3, b0, b1);
            }
        }

        // ---- online softmax in registers (rows wm+g, wm+8+g) ----
        float mx0 = m0r, mx1 = m1r;
#pragma unroll
        for (int j = 0; j < 8; j++) {
            mx0 = fmaxf(mx0, fmaxf(sc[j][0], sc[j][1]));
            mx1 = fmaxf(mx1, fmaxf(sc[j][2], sc[j][3]));
        }
        mx0 = fmaxf(mx0, __shfl_xor_sync(0xffffffffu, mx0, 1));
        mx0 = fmaxf(mx0, __shfl_xor_sync(0xffffffffu, mx0, 2));
        mx1 = fmaxf(mx1, __shfl_xor_sync(0xffffffffu, mx1, 1));
        mx1 = fmaxf(mx1, __shfl_xor_sync(0xffffffffu, mx1, 2));

        float sum0 = 0.f, sum1 = 0.f;
        unsigned ph0[8], ph1[8];
#pragma unroll
        for (int j = 0; j < 8; j++) {
            float p0 = __expf(sc[j][0] - mx0);
            float p1 = __expf(sc[j][1] - mx0);
            float p2 = __expf(sc[j][2] - mx1);
            float p3 = __expf(sc[j][3] - mx1);
            sum0 += p0 + p1; sum1 += p2 + p3;
            ph0[j] = pack_h2(p0, p1);
            ph1[j] = pack_h2(p2, p3);
        }
        sum0 += __shfl_xor_sync(0xffffffffu, sum0, 1);
        sum0 += __shfl_xor_sync(0xffffffffu, sum0, 2);
        sum1 += __shfl_xor_sync(0xffffffffu, sum1, 1);
        sum1 += __shfl_xor_sync(0xffffffffu, sum1, 2);

        float scl0 = __expf(m0r - mx0);
        float scl1 = __expf(m1r - mx1);
        l0r = l0r * scl0 + sum0;
        l1r = l1r * scl1 + sum1;
        m0r = mx0; m1r = mx1;

#pragma unroll
        for (int j = 0; j < 16; j++) {
            acc[j][0] *= scl0; acc[j][1] *= scl0;
            acc[j][2] *= scl1; acc[j][3] *= scl1;
        }

        // ---- O += P * V : warp tile 16 x 128, P from registers ----
#pragma unroll
        for (int kk = 0; kk < 4; kk++) {
            int k0 = kk * 16;
            unsigned a0 = ph0[2 * kk],     a1 = ph1[2 * kk];
            unsigned a2 = ph0[2 * kk + 1], a3 = ph1[2 * kk + 1];
#pragma unroll
            for (int j = 0; j < 16; j++) {
                unsigned b0 = *(const unsigned*)(Vs + (8 * j + g) * 72 + k0 + 2 * t);
                unsigned b1 = *(const unsigned*)(Vs + (8 * j + g) * 72 + k0 + 2 * t + 8);
                mma_f16(acc[j], a0, a1, a2, a3, b0, b1);
            }
        }
        __syncthreads();
    }

    // ---- epilogue: out = gamma * (O / l) + x ----
    const float ga = gamma_p[0];
    const float inv0 = 1.f / l0r, inv1 = 1.f / l1r;
    size_t base0 = ((size_t)b * N_ + qt * 64 + wm + g) * C_ + cs * 128;
    size_t base1 = base0 + (size_t)8 * C_;
#pragma unroll
    for (int j = 0; j < 16; j++) {
        int col = 8 * j + 2 * t;
        float2 x0 = *(const float2*)(x + base0 + col);
        float2 x1 = *(const float2*)(x + base1 + col);
        float2 o0, o1;
        o0.x = ga * acc[j][0] * inv0 + x0.x;
        o0.y = ga * acc[j][1] * inv0 + x0.y;
        o1.x = ga * acc[j][2] * inv1 + x1.x;
        o1.y = ga * acc[j][3] * inv1 + x1.y;
        *(float2*)(out + base0 + col) = o0;
        *(float2*)(out + base1 + col) = o1;
    }
}

// ---------------------------------------------------------------------------
extern "C" void kernel_launch(void* const* d_in, const int* in_sizes, int n_in,
                              void* d_out, int out_size)
{
    const float* x     = (const float*)d_in[0];
    const float* Wq    = (const float*)d_in[1];
    const float* bq    = (const float*)d_in[2];
    const float* Wk    = (const float*)d_in[3];
    const float* bk    = (const float*)d_in[4];
    const float* Wv    = (const float*)d_in[5];
    const float* bv    = (const float*)d_in[6];
    const float* gamma = (const float*)d_in[7];
    float* out = (float*)d_out;

    proj_kernel<<<dim3(10, (B_ * N_) / 64), 256>>>(x, Wq, bq, Wk, bk, Wv, bv);
    attn_kernel<<<dim3(C_ / 128, N_ / 64, B_), 128>>>(x, gamma, out);
}

// round 10
// speedup vs baseline: 7.3699x; 1.3141x over previous
#include <cuda_runtime.h>
#include <cuda_fp16.h>
#include <stdint.h>
#include <math.h>

#define B_ 16
#define N_ 2048
#define C_ 512
#define D_ 64
#define NT (N_ / 64)

__device__ __half g_Qh[B_ * N_ * D_];
__device__ __half g_Kh[B_ * N_ * D_];
__device__ __half g_Vt[B_ * C_ * N_];   // transposed: [b][c][n]
__device__ __half g_Xh[B_ * N_ * C_];
__device__ __half g_Wqh[D_ * C_];
__device__ __half g_Wkh[D_ * C_];
__device__ __half g_Wvh[C_ * C_];

// ---- fp16 mma m16n8k16, f32 accum ----
__device__ __forceinline__ void mma_f16(float c[4], unsigned a0, unsigned a1,
                                        unsigned a2, unsigned a3,
                                        unsigned b0, unsigned b1)
{
    asm volatile(
        "mma.sync.aligned.m16n8k16.row.col.f32.f16.f16.f32 "
        "{%0,%1,%2,%3}, {%4,%5,%6,%7}, {%8,%9}, {%0,%1,%2,%3};\n"
        : "+f"(c[0]), "+f"(c[1]), "+f"(c[2]), "+f"(c[3])
        : "r"(a0), "r"(a1), "r"(a2), "r"(a3), "r"(b0), "r"(b1));
}
__device__ __forceinline__ void ldsm4(unsigned& r0, unsigned& r1,
                                      unsigned& r2, unsigned& r3, uint32_t a)
{
    asm volatile("ldmatrix.sync.aligned.m8n8.x4.shared.b16 {%0,%1,%2,%3}, [%4];\n"
                 : "=r"(r0), "=r"(r1), "=r"(r2), "=r"(r3) : "r"(a));
}
__device__ __forceinline__ void cpa16(uint32_t dst, const void* src)
{
    asm volatile("cp.async.cg.shared.global [%0], [%1], 16;\n"
                 :: "r"(dst), "l"(src));
}
#define CP_COMMIT() asm volatile("cp.async.commit_group;\n" ::)
#define CP_WAIT(n)  asm volatile("cp.async.wait_group %0;\n" :: "n"(n))
__device__ __forceinline__ unsigned pack_h2(float lo, float hi) {
    __half2 h = __floats2half2_rn(lo, hi);
    return *(unsigned*)&h;
}

// ---------------------------------------------------------------------------
// f32 -> f16 convert (vectorized, n % 8 == 0)
// ---------------------------------------------------------------------------
__global__ void f2h_kernel(const float* __restrict__ in, __half* __restrict__ out,
                           int n)
{
    int i = (blockIdx.x * blockDim.x + threadIdx.x) * 8;
    if (i < n) {
        float4 v0 = *(const float4*)(in + i);
        float4 v1 = *(const float4*)(in + i + 4);
        __half2 h[4];
        h[0] = __floats2half2_rn(v0.x, v0.y);
        h[1] = __floats2half2_rn(v0.z, v0.w);
        h[2] = __floats2half2_rn(v1.x, v1.y);
        h[3] = __floats2half2_rn(v1.z, v1.w);
        *(uint4*)(out + i) = *(uint4*)h;
    }
}

// ---------------------------------------------------------------------------
// Fused fp16 projection: out[m,o] = sum_c Xh[m,c]*Wh[o,c] + bias[o]
// blockIdx.x: 0 -> Qh, 1 -> Kh, 2..9 -> Vt slice. 256 threads, double-buffered.
// Warp tile 16m x 32o. smem rows padded to 72 halves (ldmatrix conflict-free).
// ---------------------------------------------------------------------------
__global__ __launch_bounds__(256) void proj_kernel(
    const float* __restrict__ bq, const float* __restrict__ bk,
    const float* __restrict__ bv)
{
    __shared__ __half Ps[4 * 64 * 72];   // Xs[2], Ws[2]
    const uint32_t smem_u32 = (uint32_t)__cvta_generic_to_shared(Ps);
#define XS_OFF(s) ((s) * 4608)
#define WS_OFF(s) (9216 + (s) * 4608)

    const int tid = threadIdx.x;
    const int warp = tid >> 5, lane = tid & 31;
    const int g = lane >> 2, t = lane & 3;
    const int m0 = blockIdx.y * 64;
    const int wm = (warp >> 1) * 16;
    const int wn = (warp & 1) * 32;
    const int lm_row = lane & 15, lm_k = 8 * (lane >> 4);

    const __half* Wp; const float* biasp; int o0;
    if (blockIdx.x == 0)      { Wp = g_Wqh; biasp = bq; o0 = 0; }
    else if (blockIdx.x == 1) { Wp = g_Wkh; biasp = bk; o0 = 0; }
    else { o0 = (blockIdx.x - 2) * 64; Wp = g_Wvh + (size_t)o0 * C_; biasp = bv + o0; }

    const __half* Xg = g_Xh + (size_t)m0 * C_;

    float acc[4][4];
#pragma unroll
    for (int j = 0; j < 4; j++)
#pragma unroll
        for (int i = 0; i < 4; i++) acc[j][i] = 0.f;

    // prologue: stage 0 (k-chunk 0)
    {
#pragma unroll
        for (int l = 0; l < 2; l++) {
            int f = tid + l * 256;
            int row = f >> 3, c8 = (f & 7) * 8;
            cpa16(smem_u32 + (XS_OFF(0) + row * 72 + c8) * 2, Xg + (size_t)row * C_ + c8);
            cpa16(smem_u32 + (WS_OFF(0) + row * 72 + c8) * 2, Wp + (size_t)row * C_ + c8);
        }
        CP_COMMIT();
    }

    for (int kc = 0; kc < 8; kc++) {
        __syncthreads();
        if (kc + 1 < 8) {
            int s = (kc + 1) & 1, kt = (kc + 1) * 64;
#pragma unroll
            for (int l = 0; l < 2; l++) {
                int f = tid + l * 256;
                int row = f >> 3, c8 = (f & 7) * 8;
                cpa16(smem_u32 + (XS_OFF(s) + row * 72 + c8) * 2,
                      Xg + (size_t)row * C_ + kt + c8);
                cpa16(smem_u32 + (WS_OFF(s) + row * 72 + c8) * 2,
                      Wp + (size_t)row * C_ + kt + c8);
            }
            CP_COMMIT();
            CP_WAIT(1);
        } else {
            CP_WAIT(0);
        }
        __syncthreads();

        const int s = kc & 1;
        const uint32_t xs = smem_u32 + XS_OFF(s) * 2;
        const uint32_t ws = smem_u32 + WS_OFF(s) * 2;
#pragma unroll
        for (int kk = 0; kk < 4; kk++) {
            int k0 = kk * 16;
            unsigned a0, a1, a2, a3;
            ldsm4(a0, a1, a2, a3, xs + ((wm + lm_row) * 72 + k0 + lm_k) * 2);
#pragma unroll
            for (int jj = 0; jj < 2; jj++) {
                unsigned r0, r1, r2, r3;
                ldsm4(r0, r1, r2, r3,
                      ws + ((wn + 16 * jj + lm_row) * 72 + k0 + lm_k) * 2);
                mma_f16(acc[2 * jj],     a0, a1, a2, a3, r0, r2);
                mma_f16(acc[2 * jj + 1], a0, a1, a2, a3, r1, r3);
            }
        }
    }

    if (blockIdx.x < 2) {
        __half* outh = (blockIdx.x == 0) ? g_Qh : g_Kh;
#pragma unroll
        for (int j = 0; j < 4; j++) {
            int col = wn + 8 * j + 2 * t;
            float bv0 = biasp[col], bv1 = biasp[col + 1];
            __half2 h0 = __floats2half2_rn(acc[j][0] + bv0, acc[j][1] + bv1);
            __half2 h1 = __floats2half2_rn(acc[j][2] + bv0, acc[j][3] + bv1);
            *(__half2*)(outh + (size_t)(m0 + wm + g) * D_ + col) = h0;
            *(__half2*)(outh + (size_t)(m0 + wm + 8 + g) * D_ + col) = h1;
        }
    } else {
        int bb = m0 >> 11;
        int nn = m0 & (N_ - 1);
#pragma unroll
        for (int j = 0; j < 4; j++) {
            int col = wn + 8 * j + 2 * t;
            float bv0 = biasp[col], bv1 = biasp[col + 1];
            size_t c0b = ((size_t)bb * C_ + o0 + col) * N_;
            size_t c1b = c0b + N_;
            g_Vt[c0b + nn + wm + g]     = __float2half(acc[j][0] + bv0);
            g_Vt[c1b + nn + wm + g]     = __float2half(acc[j][1] + bv1);
            g_Vt[c0b + nn + wm + 8 + g] = __float2half(acc[j][2] + bv0);
            g_Vt[c1b + nn + wm + 8 + g] = __float2half(acc[j][3] + bv1);
        }
    }
#undef XS_OFF
#undef WS_OFF
}

// ---------------------------------------------------------------------------
// Flash attention: fp16 mma, ldmatrix fragments, cp.async double-buffered K/V.
// Grid (cs=4 x qt=32 x b=16), 128 threads (4 warps). Warp w: q-rows [16w,16w+16).
// smem (halves): Qs @0 (64*72), Ks[s] @4608+s*4608, Vs[s] @13824+s*9216.
// ---------------------------------------------------------------------------
__global__ __launch_bounds__(128, 3) void attn_kernel(
    const float* __restrict__ x, const float* __restrict__ gamma_p,
    float* __restrict__ out)
{
    extern __shared__ __half smh[];
    const uint32_t smem_u32 = (uint32_t)__cvta_generic_to_shared(smh);
#define KS_OFF(s) (4608 + (s) * 4608)
#define VS_OFF(s) (13824 + (s) * 9216)

    const int tid = threadIdx.x;
    const int warp = tid >> 5, lane = tid & 31;
    const int g = lane >> 2, t = lane & 3;
    const int cs = blockIdx.x, qt = blockIdx.y, b = blockIdx.z;
    const int wm = warp * 16;
    const int lm_row = lane & 15, lm_k = 8 * (lane >> 4);

    const __half* Qg = g_Qh + ((size_t)b * N_ + qt * 64) * D_;
    const __half* Kg = g_Kh + (size_t)b * N_ * D_;
    const __half* Vg = g_Vt + ((size_t)b * C_ + cs * 128) * N_;

    // prologue: Q tile + K/V stage 0, one cp.async group
    {
#pragma unroll
        for (int l = 0; l < 4; l++) {
            int f = tid + l * 128;
            int row = f >> 3, c8 = (f & 7) * 8;
            cpa16(smem_u32 + (row * 72 + c8) * 2, Qg + (size_t)row * D_ + c8);
            cpa16(smem_u32 + (KS_OFF(0) + row * 72 + c8) * 2,
                  Kg + (size_t)row * D_ + c8);
        }
#pragma unroll
        for (int l = 0; l < 8; l++) {
            int f = tid + l * 128;
            int row = f >> 3, c8 = (f & 7) * 8;
            cpa16(smem_u32 + (VS_OFF(0) + row * 72 + c8) * 2,
                  Vg + (size_t)row * N_ + c8);
        }
        CP_COMMIT();
    }

    float m0r = -INFINITY, m1r = -INFINITY, l0r = 0.f, l1r = 0.f;
    float acc[16][4];
#pragma unroll
    for (int j = 0; j < 16; j++)
#pragma unroll
        for (int i = 0; i < 4; i++) acc[j][i] = 0.f;

    for (int mt = 0; mt < NT; mt++) {
        __syncthreads();   // protect stage being overwritten below
        if (mt + 1 < NT) {
            int s = (mt + 1) & 1, n0g = (mt + 1) * 64;
#pragma unroll
            for (int l = 0; l < 4; l++) {
                int f = tid + l * 128;
                int row = f >> 3, c8 = (f & 7) * 8;
                cpa16(smem_u32 + (KS_OFF(s) + row * 72 + c8) * 2,
                      Kg + (size_t)(n0g + row) * D_ + c8);
            }
#pragma unroll
            for (int l = 0; l < 8; l++) {
                int f = tid + l * 128;
                int row = f >> 3, c8 = (f & 7) * 8;
                cpa16(smem_u32 + (VS_OFF(s) + row * 72 + c8) * 2,
                      Vg + (size_t)row * N_ + n0g + c8);
            }
            CP_COMMIT();
            CP_WAIT(1);
        } else {
            CP_WAIT(0);
        }
        __syncthreads();

        const int s = mt & 1;
        const uint32_t ks = smem_u32 + KS_OFF(s) * 2;
        const uint32_t vs = smem_u32 + VS_OFF(s) * 2;

        // ---- S = Q * K^T : warp tile 16 x 64 ----
        float sc[8][4];
#pragma unroll
        for (int j = 0; j < 8; j++)
#pragma unroll
            for (int i = 0; i < 4; i++) sc[j][i] = 0.f;
#pragma unroll
        for (int kk = 0; kk < 4; kk++) {
            int k0 = kk * 16;
            unsigned a0, a1, a2, a3;
            ldsm4(a0, a1, a2, a3,
                  smem_u32 + ((wm + lm_row) * 72 + k0 + lm_k) * 2);
#pragma unroll
            for (int jj = 0; jj < 4; jj++) {
                unsigned r0, r1, r2, r3;
                ldsm4(r0, r1, r2, r3, ks + ((16 * jj + lm_row) * 72 + k0 + lm_k) * 2);
                mma_f16(sc[2 * jj],     a0, a1, a2, a3, r0, r2);
                mma_f16(sc[2 * jj + 1], a0, a1, a2, a3, r1, r3);
            }
        }

        // ---- online softmax in registers ----
        float mx0 = m0r, mx1 = m1r;
#pragma unroll
        for (int j = 0; j < 8; j++) {
            mx0 = fmaxf(mx0, fmaxf(sc[j][0], sc[j][1]));
            mx1 = fmaxf(mx1, fmaxf(sc[j][2], sc[j][3]));
        }
        mx0 = fmaxf(mx0, __shfl_xor_sync(0xffffffffu, mx0, 1));
        mx0 = fmaxf(mx0, __shfl_xor_sync(0xffffffffu, mx0, 2));
        mx1 = fmaxf(mx1, __shfl_xor_sync(0xffffffffu, mx1, 1));
        mx1 = fmaxf(mx1, __shfl_xor_sync(0xffffffffu, mx1, 2));

        float sum0 = 0.f, sum1 = 0.f;
        unsigned ph0[8], ph1[8];
#pragma unroll
        for (int j = 0; j < 8; j++) {
            float p0 = __expf(sc[j][0] - mx0);
            float p1 = __expf(sc[j][1] - mx0);
            float p2 = __expf(sc[j][2] - mx1);
            float p3 = __expf(sc[j][3] - mx1);
            sum0 += p0 + p1; sum1 += p2 + p3;
            ph0[j] = pack_h2(p0, p1);
            ph1[j] = pack_h2(p2, p3);
        }
        sum0 += __shfl_xor_sync(0xffffffffu, sum0, 1);
        sum0 += __shfl_xor_sync(0xffffffffu, sum0, 2);
        sum1 += __shfl_xor_sync(0xffffffffu, sum1, 1);
        sum1 += __shfl_xor_sync(0xffffffffu, sum1, 2);

        float scl0 = __expf(m0r - mx0);
        float scl1 = __expf(m1r - mx1);
        l0r = l0r * scl0 + sum0;
        l1r = l1r * scl1 + sum1;
        m0r = mx0; m1r = mx1;

#pragma unroll
        for (int j = 0; j < 16; j++) {
            acc[j][0] *= scl0; acc[j][1] *= scl0;
            acc[j][2] *= scl1; acc[j][3] *= scl1;
        }

        // ---- O += P * V : warp tile 16 x 128, P from registers ----
#pragma unroll
        for (int kk = 0; kk < 4; kk++) {
            int k0 = kk * 16;
            unsigned a0 = ph0[2 * kk],     a1 = ph1[2 * kk];
            unsigned a2 = ph0[2 * kk + 1], a3 = ph1[2 * kk + 1];
#pragma unroll
            for (int jj = 0; jj < 8; jj++) {
                unsigned r0, r1, r2, r3;
                ldsm4(r0, r1, r2, r3, vs + ((16 * jj + lm_row) * 72 + k0 + lm_k) * 2);
                mma_f16(acc[2 * jj],     a0, a1, a2, a3, r0, r2);
                mma_f16(acc[2 * jj + 1], a0, a1, a2, a3, r1, r3);
            }
        }
    }

    // ---- epilogue: out = gamma * (O / l) + x ----
    const float ga = gamma_p[0];
    const float inv0 = 1.f / l0r, inv1 = 1.f / l1r;
    size_t base0 = ((size_t)b * N_ + qt * 64 + wm + g) * C_ + cs * 128;
    size_t base1 = base0 + (size_t)8 * C_;
#pragma unroll
    for (int j = 0; j < 16; j++) {
        int col = 8 * j + 2 * t;
        float2 x0 = *(const float2*)(x + base0 + col);
        float2 x1 = *(const float2*)(x + base1 + col);
        float2 o0, o1;
        o0.x = ga * acc[j][0] * inv0 + x0.x;
        o0.y = ga * acc[j][1] * inv0 + x0.y;
        o1.x = ga * acc[j][2] * inv1 + x1.x;
        o1.y = ga * acc[j][3] * inv1 + x1.y;
        *(float2*)(out + base0 + col) = o0;
        *(float2*)(out + base1 + col) = o1;
    }
#undef KS_OFF
#undef VS_OFF
}

// ---------------------------------------------------------------------------
extern "C" void kernel_launch(void* const* d_in, const int* in_sizes, int n_in,
                              void* d_out, int out_size)
{
    const float* x     = (const float*)d_in[0];
    const float* Wq    = (const float*)d_in[1];
    const float* bq    = (const float*)d_in[2];
    const float* Wk    = (const float*)d_in[3];
    const float* bk    = (const float*)d_in[4];
    const float* Wv    = (const float*)d_in[5];
    const float* bv    = (const float*)d_in[6];
    const float* gamma = (const float*)d_in[7];
    float* out = (float*)d_out;

    __half *xh, *wqh, *wkh, *wvh;
    cudaGetSymbolAddress((void**)&xh,  g_Xh);
    cudaGetSymbolAddress((void**)&wqh, g_Wqh);
    cudaGetSymbolAddress((void**)&wkh, g_Wkh);
    cudaGetSymbolAddress((void**)&wvh, g_Wvh);

    const int nx = B_ * N_ * C_;
    f2h_kernel<<<nx / (256 * 8), 256>>>(x, xh, nx);
    f2h_kernel<<<(D_ * C_) / (256 * 8), 256>>>(Wq, wqh, D_ * C_);
    f2h_kernel<<<(D_ * C_) / (256 * 8), 256>>>(Wk, wkh, D_ * C_);
    f2h_kernel<<<(C_ * C_) / (256 * 8), 256>>>(Wv, wvh, C_ * C_);

    proj_kernel<<<dim3(10, (B_ * N_) / 64), 256>>>(bq, bk, bv);

    const int smem_bytes = 32256 * 2;   // 64512
    cudaFuncSetAttribute(attn_kernel,
                         cudaFuncAttributeMaxDynamicSharedMemorySize, smem_bytes);
    attn_kernel<<<dim3(C_ / 128, N_ / 64, B_), 128, smem_bytes>>>(x, gamma, out);
}